// round 1
// baseline (speedup 1.0000x reference)
#include <cuda_runtime.h>
#include <cstdint>

// Problem constants (from reference)
#define BB   16
#define DD   64
#define LL   2048
#define KK   1000
#define KPAD 1024
#define NN   (BB * LL)          // 32768 tokens
#define TM   128                // tokens per block
#define KC   128                // codes per chunk
#define NCHUNK (KPAD / KC)      // 8
#define THREADS 256
#define XS_STRIDE 132           // [d][t] padded, %4==0 for float4/b64, %32!=0
#define ES_STRIDE 68            // [k][d] padded, %4==0 for float4

#define OUT_ELEMS (BB * DD * LL)     // 2097152
#define LOSS_OFF  OUT_ELEMS          // 2097152
#define USAGE_OFF (OUT_ELEMS + 1)    // 2097153
#define IDX_OFF   (OUT_ELEMS + 2)    // 2097154

__device__ float g_enorm[KPAD];
__device__ int   g_flags[KK];
__device__ float g_loss;

// ---- packed f32x2 helpers (Blackwell FFMA2 path) ----
__device__ __forceinline__ unsigned long long ffma2(unsigned long long a,
                                                    unsigned long long b,
                                                    unsigned long long c) {
    unsigned long long d;
    asm("fma.rn.f32x2 %0, %1, %2, %3;" : "=l"(d) : "l"(a), "l"(b), "l"(c));
    return d;
}
__device__ __forceinline__ unsigned long long dup2(float v) {
    unsigned long long r;
    asm("mov.b64 %0, {%1, %1};" : "=l"(r) : "f"(v));
    return r;
}
__device__ __forceinline__ void unpack2(unsigned long long v, float& lo, float& hi) {
    asm("mov.b64 {%0, %1}, %2;" : "=f"(lo), "=f"(hi) : "l"(v));
}

// ---- prep: per-code squared norms, clear flags & loss accumulator ----
__global__ void vq_prep(const float* __restrict__ emb) {
    int t = threadIdx.x;
    if (t == 0) g_loss = 0.0f;
    if (t < KK) {
        const float* row = emb + (size_t)t * DD;
        float s = 0.0f;
        #pragma unroll
        for (int d = 0; d < DD; d++) s += row[d] * row[d];
        g_enorm[t] = s;
        g_flags[t] = 0;
    } else if (t < KPAD) {
        g_enorm[t] = 3.4e38f;   // padded codes never win
    }
}

// ---- main: distances + argmin + gather + loss partial ----
__global__ void __launch_bounds__(THREADS, 2)
vq_main(const float* __restrict__ x, const float* __restrict__ emb,
        float* __restrict__ dout) {
    extern __shared__ float sm[];
    float* xs  = sm;                               // [64][XS_STRIDE]
    float* es  = xs + DD * XS_STRIDE;              // [KC][ES_STRIDE]
    float* se  = es + KC * ES_STRIDE;              // [KC] code norms
    float* xns = se + KC;                          // [TM] token norms
    float* rv  = xns + TM;                         // [16][TM] reduce vals
    int*   ri  = (int*)(rv + 16 * TM);             // [16][TM] reduce idx
    int*   ii  = ri + 16 * TM;                     // [TM] final idx

    const int tid = threadIdx.x;
    const int b  = blockIdx.x >> 4;
    const int l0 = (blockIdx.x & 15) * TM;
    const int tt = tid & 15;    // token group  (8 tokens)
    const int tc = tid >> 4;    // code  group  (8 codes)

    // Load x tile [64][128] transposed to [d][t], coalesced float4
    for (int i = tid; i < DD * (TM / 4); i += THREADS) {
        int d = i >> 5, t4 = i & 31;
        float4 v = *(const float4*)(x + ((size_t)(b * DD + d)) * LL + l0 + t4 * 4);
        *(float4*)(xs + d * XS_STRIDE + t4 * 4) = v;
    }
    __syncthreads();

    // Per-token squared norms (conflict-free column reads)
    if (tid < TM) {
        float s = 0.0f;
        #pragma unroll
        for (int d = 0; d < DD; d++) {
            float v = xs[d * XS_STRIDE + tid];
            s += v * v;
        }
        xns[tid] = s;
    }

    float bestv[8];
    int   besti[8];
    #pragma unroll
    for (int i = 0; i < 8; i++) { bestv[i] = 3.0e38f; besti[i] = 0; }

    for (int c = 0; c < NCHUNK; c++) {
        const int k0 = c * KC;
        __syncthreads();
        // Load code chunk [KC][64], row-major (reads broadcast later)
        for (int i = tid; i < KC * (DD / 4); i += THREADS) {
            int k = i >> 4, d4 = i & 15;
            float4 v = make_float4(0.f, 0.f, 0.f, 0.f);
            if (k0 + k < KK)
                v = *(const float4*)(emb + (size_t)(k0 + k) * DD + d4 * 4);
            *(float4*)(es + k * ES_STRIDE + d4 * 4) = v;
        }
        if (tid < KC) se[tid] = g_enorm[k0 + tid];
        __syncthreads();

        // 8 tokens x 8 codes register tile, tokens packed in f32x2 pairs
        unsigned long long acc[8][4];
        #pragma unroll
        for (int j = 0; j < 8; j++)
            #pragma unroll
            for (int p = 0; p < 4; p++) acc[j][p] = 0ull;

        const float* erow = es + (tc * 8) * ES_STRIDE;
        #pragma unroll 2
        for (int d = 0; d < DD; d++) {
            const unsigned long long* xv =
                (const unsigned long long*)(xs + d * XS_STRIDE + tt * 8);
            unsigned long long xp0 = xv[0], xp1 = xv[1], xp2 = xv[2], xp3 = xv[3];
            #pragma unroll
            for (int j = 0; j < 8; j++) {
                unsigned long long e2 = dup2(erow[j * ES_STRIDE + d]);
                acc[j][0] = ffma2(xp0, e2, acc[j][0]);
                acc[j][1] = ffma2(xp1, e2, acc[j][1]);
                acc[j][2] = ffma2(xp2, e2, acc[j][2]);
                acc[j][3] = ffma2(xp3, e2, acc[j][3]);
            }
        }

        // argmin update: metric m = ||e||^2 - 2*dot  (||x||^2 added later)
        #pragma unroll
        for (int j = 0; j < 8; j++) {
            int   kk = k0 + tc * 8 + j;
            float en = se[tc * 8 + j];
            #pragma unroll
            for (int p = 0; p < 4; p++) {
                float d0, d1;
                unpack2(acc[j][p], d0, d1);
                float m0 = en - 2.0f * d0;
                float m1 = en - 2.0f * d1;
                int t0 = 2 * p, t1 = 2 * p + 1;
                if (m0 < bestv[t0]) { bestv[t0] = m0; besti[t0] = kk; }
                if (m1 < bestv[t1]) { bestv[t1] = m1; besti[t1] = kk; }
            }
        }
    }

    // Cross-thread (over tc) argmin reduction
    __syncthreads();
    #pragma unroll
    for (int i = 0; i < 8; i++) {
        rv[tc * TM + tt * 8 + i] = bestv[i];
        ri[tc * TM + tt * 8 + i] = besti[i];
    }
    __syncthreads();

    if (tid < TM) {
        float bv = rv[tid];
        int   bi = ri[tid];
        #pragma unroll
        for (int g = 1; g < 16; g++) {
            float v  = rv[g * TM + tid];
            int   ix = ri[g * TM + tid];
            if (v < bv || (v == bv && ix < bi)) { bv = v; bi = ix; }
        }
        int n = b * LL + l0 + tid;
        dout[IDX_OFF + n] = (float)bi;
        g_flags[bi] = 1;            // idempotent mark
        ii[tid] = bi;
        rv[tid] = xns[tid] + bv;    // min squared distance for loss
    }
    __syncthreads();

    // Block loss reduction (first 128 slots of rv)
    if (tid < 64) rv[tid] += rv[tid + 64];
    __syncthreads();
    if (tid < 32) {
        float s = rv[tid] + rv[tid + 32];
        #pragma unroll
        for (int off = 16; off > 0; off >>= 1)
            s += __shfl_down_sync(0xffffffffu, s, off);
        if (tid == 0) atomicAdd(&g_loss, s);
    }

    // Gather + transpose write: out[b][d][l] = emb[idx][d] (coalesced stores)
    __syncthreads();
    for (int i = tid; i < DD * TM; i += THREADS) {
        int d = i >> 7, t = i & 127;
        dout[((size_t)(b * DD + d)) * LL + l0 + t] = emb[(size_t)ii[t] * DD + d];
    }
}

// ---- finalize: usage count + loss scalar ----
__global__ void vq_final(float* __restrict__ dout) {
    __shared__ int cnt;
    if (threadIdx.x == 0) cnt = 0;
    __syncthreads();
    int c = 0;
    for (int i = threadIdx.x; i < KK; i += blockDim.x) c += g_flags[i];
    #pragma unroll
    for (int off = 16; off > 0; off >>= 1)
        c += __shfl_down_sync(0xffffffffu, c, off);
    if ((threadIdx.x & 31) == 0) atomicAdd(&cnt, c);
    __syncthreads();
    if (threadIdx.x == 0) {
        dout[LOSS_OFF]  = 11.0f * g_loss / (float)(NN * DD);  // (1 + 10) * MSE
        dout[USAGE_OFF] = (float)cnt;
    }
}

extern "C" void kernel_launch(void* const* d_in, const int* in_sizes, int n_in,
                              void* d_out, int out_size) {
    (void)n_in; (void)out_size;
    // Identify inputs by size (x: 2097152, emb: 64000)
    const float* x;
    const float* emb;
    if (in_sizes[0] == KK * DD) { emb = (const float*)d_in[0]; x = (const float*)d_in[1]; }
    else                        { x   = (const float*)d_in[0]; emb = (const float*)d_in[1]; }
    float* out = (float*)d_out;

    const int smem_bytes =
        (DD * XS_STRIDE + KC * ES_STRIDE + KC + TM + 16 * TM) * 4  // floats
        + (16 * TM + TM) * 4;                                      // ints
    cudaFuncSetAttribute(vq_main, cudaFuncAttributeMaxDynamicSharedMemorySize,
                         smem_bytes);

    vq_prep<<<1, KPAD>>>(emb);
    vq_main<<<NN / TM, THREADS, smem_bytes>>>(x, emb, out);
    vq_final<<<1, 256>>>(out);
}

// round 2
// speedup vs baseline: 1.6094x; 1.6094x over previous
#include <cuda_runtime.h>
#include <cstdint>

// Problem constants (from reference)
#define BB   16
#define DD   64
#define LL   2048
#define KK   1000
#define KPAD 1024
#define NN   (BB * LL)          // 32768 tokens
#define TM   128                // tokens per block
#define KC   128                // codes per chunk
#define NCHUNK (KPAD / KC)      // 8
#define THREADS 256
#define NBLK (NN / TM)          // 256 blocks
#define XS_STRIDE 132           // [d][t] padded, %4==0 for float4/b64
#define ES_STRIDE 68            // [k][d] padded, %4==0 for float4

#define OUT_ELEMS (BB * DD * LL)     // 2097152
#define LOSS_OFF  OUT_ELEMS          // 2097152
#define USAGE_OFF (OUT_ELEMS + 1)    // 2097153
#define IDX_OFF   (OUT_ELEMS + 2)    // 2097154

// Per-block loss partials: written by every block on every call, never needs
// clearing (deterministic, graph-replay safe).
__device__ float g_partial[NBLK];

// ---- packed f32x2 helpers (Blackwell FFMA2 path) ----
__device__ __forceinline__ unsigned long long ffma2(unsigned long long a,
                                                    unsigned long long b,
                                                    unsigned long long c) {
    unsigned long long d;
    asm("fma.rn.f32x2 %0, %1, %2, %3;" : "=l"(d) : "l"(a), "l"(b), "l"(c));
    return d;
}
__device__ __forceinline__ unsigned long long dup2(float v) {
    unsigned long long r;
    asm("mov.b64 %0, {%1, %1};" : "=l"(r) : "f"(v));
    return r;
}
__device__ __forceinline__ void unpack2(unsigned long long v, float& lo, float& hi) {
    asm("mov.b64 {%0, %1}, %2;" : "=f"(lo), "=f"(hi) : "l"(v));
}

// ---- main: distances + argmin + gather + loss partial ----
__global__ void __launch_bounds__(THREADS, 2)
vq_main(const float* __restrict__ x, const float* __restrict__ emb,
        float* __restrict__ dout) {
    extern __shared__ float sm[];
    float* xs  = sm;                               // [64][XS_STRIDE]
    float* es  = xs + DD * XS_STRIDE;              // [KC][ES_STRIDE]
    float* se  = es + KC * ES_STRIDE;              // [KC] code norms
    float* xns = se + KC;                          // [TM] token norms
    float* rv  = xns + TM;                         // [16][TM] reduce vals
    int*   ri  = (int*)(rv + 16 * TM);             // [16][TM] reduce idx
    int*   ii  = ri + 16 * TM;                     // [TM] final idx

    const int tid = threadIdx.x;
    const int b  = blockIdx.x >> 4;
    const int l0 = (blockIdx.x & 15) * TM;
    const int tt = tid & 15;    // token group (8 tokens as 4 adjacent pairs)
    const int tc = tid >> 4;    // code  group (8 codes)

    // Load x tile [64][128] transposed to [d][t], coalesced float4
    for (int i = tid; i < DD * (TM / 4); i += THREADS) {
        int d = i >> 5, t4 = i & 31;
        float4 v = *(const float4*)(x + ((size_t)(b * DD + d)) * LL + l0 + t4 * 4);
        *(float4*)(xs + d * XS_STRIDE + t4 * 4) = v;
    }
    __syncthreads();

    // Per-token squared norms (conflict-free column reads)
    if (tid < TM) {
        float s = 0.0f;
        #pragma unroll
        for (int d = 0; d < DD; d++) {
            float v = xs[d * XS_STRIDE + tid];
            s += v * v;
        }
        xns[tid] = s;
    }

    float bestv[8];
    int   besti[8];
    #pragma unroll
    for (int i = 0; i < 8; i++) { bestv[i] = 3.0e38f; besti[i] = 0; }

    for (int c = 0; c < NCHUNK; c++) {
        const int k0 = c * KC;
        __syncthreads();
        // Load code chunk [KC][64] (coalesced float4; zero-pad past KK)
        for (int i = tid; i < KC * (DD / 4); i += THREADS) {
            int k = i >> 4, d4 = i & 15;
            float4 v = make_float4(0.f, 0.f, 0.f, 0.f);
            if (k0 + k < KK)
                v = *(const float4*)(emb + (size_t)(k0 + k) * DD + d4 * 4);
            *(float4*)(es + k * ES_STRIDE + d4 * 4) = v;
        }
        __syncthreads();
        // In-block code norms (kills the serial prep kernel)
        if (tid < KC) {
            if (k0 + tid < KK) {
                const float* row = es + tid * ES_STRIDE;
                float s = 0.0f;
                #pragma unroll
                for (int d4 = 0; d4 < DD / 4; d4++) {
                    float4 v = *(const float4*)(row + d4 * 4);
                    s += v.x * v.x + v.y * v.y + v.z * v.z + v.w * v.w;
                }
                se[tid] = s;
            } else {
                se[tid] = 3.4e38f;  // padded codes never win
            }
        }
        __syncthreads();

        // 8 tokens x 8 codes register tile, token pairs packed in f32x2.
        // Token mapping: pair p holds tokens (2*tt + 32*p, 2*tt + 32*p + 1)
        // -> b64 smem index tt + 16*p -> banks 2*tt%32: conflict-free.
        unsigned long long acc[8][4];
        #pragma unroll
        for (int j = 0; j < 8; j++)
            #pragma unroll
            for (int p = 0; p < 4; p++) acc[j][p] = 0ull;

        const float* erow = es + (tc * 8) * ES_STRIDE;
        #pragma unroll 2
        for (int d = 0; d < DD; d++) {
            const unsigned long long* xrow =
                (const unsigned long long*)(xs + d * XS_STRIDE);
            unsigned long long xp0 = xrow[tt];
            unsigned long long xp1 = xrow[tt + 16];
            unsigned long long xp2 = xrow[tt + 32];
            unsigned long long xp3 = xrow[tt + 48];
            #pragma unroll
            for (int j = 0; j < 8; j++) {
                unsigned long long e2 = dup2(erow[j * ES_STRIDE + d]);
                acc[j][0] = ffma2(xp0, e2, acc[j][0]);
                acc[j][1] = ffma2(xp1, e2, acc[j][1]);
                acc[j][2] = ffma2(xp2, e2, acc[j][2]);
                acc[j][3] = ffma2(xp3, e2, acc[j][3]);
            }
        }

        // argmin update: metric m = ||e||^2 - 2*dot  (||x||^2 added later)
        #pragma unroll
        for (int j = 0; j < 8; j++) {
            int   kk = k0 + tc * 8 + j;
            float en = se[tc * 8 + j];
            #pragma unroll
            for (int p = 0; p < 4; p++) {
                float d0, d1;
                unpack2(acc[j][p], d0, d1);
                float m0 = fmaf(-2.0f, d0, en);
                float m1 = fmaf(-2.0f, d1, en);
                int s0 = 2 * p, s1 = 2 * p + 1;
                if (m0 < bestv[s0]) { bestv[s0] = m0; besti[s0] = kk; }
                if (m1 < bestv[s1]) { bestv[s1] = m1; besti[s1] = kk; }
            }
        }
    }

    // Cross-thread (over tc) argmin reduction
    __syncthreads();
    #pragma unroll
    for (int p = 0; p < 4; p++) {
        int t = 2 * tt + 32 * p;
        rv[tc * TM + t]     = bestv[2 * p];
        ri[tc * TM + t]     = besti[2 * p];
        rv[tc * TM + t + 1] = bestv[2 * p + 1];
        ri[tc * TM + t + 1] = besti[2 * p + 1];
    }
    __syncthreads();

    if (tid < TM) {
        float bv = rv[tid];
        int   bi = ri[tid];
        #pragma unroll
        for (int g = 1; g < 16; g++) {
            float v  = rv[g * TM + tid];
            int   ix = ri[g * TM + tid];
            if (v < bv || (v == bv && ix < bi)) { bv = v; bi = ix; }
        }
        int n = b * LL + l0 + tid;
        dout[IDX_OFF + n] = (float)bi;
        ii[tid] = bi;
        rv[tid] = xns[tid] + bv;    // min squared distance for loss
    }
    __syncthreads();

    // Block loss reduction -> per-block partial (no global clear needed)
    if (tid < 64) rv[tid] += rv[tid + 64];
    __syncthreads();
    if (tid < 32) {
        float s = rv[tid] + rv[tid + 32];
        #pragma unroll
        for (int off = 16; off > 0; off >>= 1)
            s += __shfl_down_sync(0xffffffffu, s, off);
        if (tid == 0) g_partial[blockIdx.x] = s;
    }

    // Gather + transpose write: out[b][d][l] = emb[idx][d] (coalesced stores)
    __syncthreads();
    for (int i = tid; i < DD * TM; i += THREADS) {
        int d = i >> 7, t = i & 127;
        dout[((size_t)(b * DD + d)) * LL + l0 + t] = emb[(size_t)ii[t] * DD + d];
    }
}

// ---- finalize: usage count (from idx output) + loss scalar ----
__global__ void __launch_bounds__(1024, 1)
vq_final(float* __restrict__ dout) {
    __shared__ int   flags[KK];
    __shared__ int   cnt;
    __shared__ float lsum;
    int tid = threadIdx.x;
    if (tid == 0) { cnt = 0; lsum = 0.0f; }
    for (int i = tid; i < KK; i += 1024) flags[i] = 0;
    __syncthreads();

    // mark used codes from the idx output
    for (int i = tid; i < NN; i += 1024) {
        int k = (int)dout[IDX_OFF + i];
        flags[k] = 1;
    }
    // sum loss partials
    float s = 0.0f;
    if (tid < NBLK) s = g_partial[tid];
    #pragma unroll
    for (int off = 16; off > 0; off >>= 1)
        s += __shfl_down_sync(0xffffffffu, s, off);
    if ((tid & 31) == 0 && tid < NBLK) atomicAdd(&lsum, s);
    __syncthreads();

    int c = 0;
    for (int i = tid; i < KK; i += 1024) c += flags[i];
    #pragma unroll
    for (int off = 16; off > 0; off >>= 1)
        c += __shfl_down_sync(0xffffffffu, c, off);
    if ((tid & 31) == 0) atomicAdd(&cnt, c);
    __syncthreads();

    if (tid == 0) {
        dout[LOSS_OFF]  = 11.0f * lsum / (float)(NN * DD);  // (1 + 10) * MSE
        dout[USAGE_OFF] = (float)cnt;
    }
}

extern "C" void kernel_launch(void* const* d_in, const int* in_sizes, int n_in,
                              void* d_out, int out_size) {
    (void)n_in; (void)out_size;
    const float* x;
    const float* emb;
    if (in_sizes[0] == KK * DD) { emb = (const float*)d_in[0]; x = (const float*)d_in[1]; }
    else                        { x   = (const float*)d_in[0]; emb = (const float*)d_in[1]; }
    float* out = (float*)d_out;

    const int smem_bytes =
        (DD * XS_STRIDE + KC * ES_STRIDE + KC + TM + 16 * TM) * 4  // floats
        + (16 * TM + TM) * 4;                                      // ints
    cudaFuncSetAttribute(vq_main, cudaFuncAttributeMaxDynamicSharedMemorySize,
                         smem_bytes);

    vq_main<<<NBLK, THREADS, smem_bytes>>>(x, emb, out);
    vq_final<<<1, 1024>>>(out);
}